// round 11
// baseline (speedup 1.0000x reference)
#include <cuda_runtime.h>
#include <cuda_bf16.h>
#include <cstdint>

// TorchBiRNN: B=64, T=512, I=128, H=256 bidirectional tanh RNN.
// Phase 1: pre[d][t][b][h] = x[b][t][:]·w_ih_d[h][:] + b_ih_d[h] + b_hh_d[h]
// Phase 2: CLUSTERLESS (R7 topology). 128 CTAs, one per (batch,dir).
//          Thread (j = tid&127, c = tid>>7): rows {j, j+128}, k in
//          [128c,128c+128). Split per row: 88 k in regs, 40 k streamed from
//          smem. 4 accumulator chains; free regs for ptxas pipelining.
// R11 fix: h read base for c=1 is 132 (padded layout), not 128.

#define OUT_YS (64 * 512 * 512)
#define NRQ 22              // reg k-quads per row  (88 floats)
#define NSQ 10              // smem k-quads per row (40 floats)
#define STEP_SMEM (81920 + 2080 + 512 + 512)   // ws4 + h_buf + redA + redB

__device__ float g_pre[2 * 512 * 64 * 256];   // 64 MB scratch (module-static)

// ---------------- helpers ----------------
__device__ __forceinline__ unsigned long long ffma2(unsigned long long a,
                                                    unsigned long long b,
                                                    unsigned long long c) {
    unsigned long long d;
    asm("fma.rn.f32x2 %0, %1, %2, %3;" : "=l"(d) : "l"(a), "l"(b), "l"(c));
    return d;
}
__device__ __forceinline__ unsigned long long pack2(float a, float b) {
    unsigned long long r;
    asm("mov.b64 %0, {%1, %2};" : "=l"(r) : "f"(a), "f"(b));
    return r;
}
__device__ __forceinline__ float sum2(unsigned long long v) {
    float2 f;
    asm("mov.b64 {%0, %1}, %2;" : "=f"(f.x), "=f"(f.y) : "l"(v));
    return f.x + f.y;
}
__device__ __forceinline__ float fast_tanh(float x) {
    float e = __expf(2.0f * x);
    return 1.0f - __fdividef(2.0f, e + 1.0f);
}

// ---------------------------------------------------------------------------
// Phase 1: GEMM. M=32768 (m = t*64+b), N=256, K=128 staged by 64.
// 64x64 tile, 256 threads, 4x4 microtile, FFMA2, XOR-swizzled smem.
// ---------------------------------------------------------------------------
__global__ __launch_bounds__(256, 2) void pre_gemm_kernel(
    const float* __restrict__ x,
    const float* __restrict__ w_ih_f, const float* __restrict__ b_ih_f,
    const float* __restrict__ b_hh_f,
    const float* __restrict__ w_ih_b, const float* __restrict__ b_ih_b,
    const float* __restrict__ b_hh_b)
{
    __shared__ __align__(16) float4 xs4[64][16];
    __shared__ __align__(16) float4 ws4[64][16];

    const int bx = blockIdx.x;
    const int d  = bx >> 11;
    const int mt = (bx & 2047) >> 2;
    const int nt = bx & 3;
    const float* __restrict__ w_ih = d ? w_ih_b : w_ih_f;
    const float* __restrict__ bi   = d ? b_ih_b : b_ih_f;
    const float* __restrict__ bh   = d ? b_hh_b : b_hh_f;
    const int m0 = mt << 6, n0 = nt << 6;
    const int tid = threadIdx.x;
    const int tm = tid & 15, tn = tid >> 4;

    unsigned long long acc[4][4];
#pragma unroll
    for (int m = 0; m < 4; m++)
#pragma unroll
        for (int n = 0; n < 4; n++) acc[m][n] = 0ull;

#pragma unroll
    for (int ks = 0; ks < 128; ks += 64) {
#pragma unroll
        for (int i = 0; i < 4; i++) {
            int idx = tid + (i << 8);
            int r = idx >> 4, c4 = idx & 15;
            int sw = c4 ^ ((r >> 2) & 7);
            int m = m0 + r;
            int t = m >> 6, b = m & 63;
            xs4[r][sw] = *(const float4*)(x + ((size_t)(b << 9) + t) * 128 + ks + (c4 << 2));
            ws4[r][sw] = *(const float4*)(w_ih + ((size_t)(n0 + r) << 7) + ks + (c4 << 2));
        }
        __syncthreads();
#pragma unroll
        for (int k4 = 0; k4 < 16; k4++) {
            ulonglong2 a2[4], b2[4];
#pragma unroll
            for (int m = 0; m < 4; m++)
                a2[m] = *(const ulonglong2*)&xs4[(tm << 2) + m][k4 ^ (tm & 7)];
#pragma unroll
            for (int n = 0; n < 4; n++)
                b2[n] = *(const ulonglong2*)&ws4[(tn << 2) + n][k4 ^ (tn & 7)];
#pragma unroll
            for (int m = 0; m < 4; m++)
#pragma unroll
                for (int n = 0; n < 4; n++) {
                    acc[m][n] = ffma2(a2[m].x, b2[n].x, acc[m][n]);
                    acc[m][n] = ffma2(a2[m].y, b2[n].y, acc[m][n]);
                }
        }
        __syncthreads();
    }

    const int nbase = n0 + (tn << 2);
    float4 bi4 = *(const float4*)(bi + nbase);
    float4 bh4 = *(const float4*)(bh + nbase);
    float4 bias;
    bias.x = bi4.x + bh4.x; bias.y = bi4.y + bh4.y;
    bias.z = bi4.z + bh4.z; bias.w = bi4.w + bh4.w;

#pragma unroll
    for (int m = 0; m < 4; m++) {
        int mrow = m0 + (tm << 2) + m;
        float4 o;
        o.x = sum2(acc[m][0]) + bias.x;
        o.y = sum2(acc[m][1]) + bias.y;
        o.z = sum2(acc[m][2]) + bias.z;
        o.w = sum2(acc[m][3]) + bias.w;
        *(float4*)(g_pre + ((size_t)(d * 32768 + mrow)) * 256 + nbase) = o;
    }
}

// ---------------------------------------------------------------------------
// Phase 2: recurrence. Grid 128 (one CTA per (batch,dir)), 256 threads.
// Thread (j = tid&127, c = tid>>7): rows {j, j+128}, k in [128c, 128c+128).
//   k-quads 0..21 of the window: weights in regs (44 ull per row).
//   k-quads 22..31: weights in smem ws4[cc][r2][kq][j] (80 KB).
// h per buffer: 260 floats, k>=128 stored at k+4 (writer j+132, reader base
// 132 for c=1). h quads are warp-uniform broadcast LDS.
// Dyn smem: 81920 (ws4) + 2080 (h_buf) + 512 (redA) + 512 (redB) = 85024 B.
// ---------------------------------------------------------------------------
__global__ __launch_bounds__(256, 1)
void rnn_step_kernel(const float* __restrict__ w_hh_f,
                     const float* __restrict__ w_hh_b,
                     float* __restrict__ out)
{
    extern __shared__ __align__(16) char smem_raw[];
    float4* ws4   = (float4*)smem_raw;                    // [2][2][NSQ][128]
    float*  h_buf = (float*)(smem_raw + 81920);           // [2][260]
    float*  redA  = h_buf + 520;                          // [128] c1 partial (row j)
    float*  redB  = redA + 128;                           // [128] c0 partial (row j+128)

    const int id  = blockIdx.x;
    const int d   = id >> 6;
    const int b   = id & 63;
    const int tid = threadIdx.x;
    const int j   = tid & 127;
    const int c   = tid >> 7;

    const float* __restrict__ w_hh = d ? w_hh_b : w_hh_f;

    // --- fill smem weights: ws4[((cc*2+r2)*NSQ+kq)*128 + jj]
    //     = w[r2*128+jj][cc*128 + 4*NRQ + 4*kq ...+3]
    for (int i = tid; i < 2 * 2 * NSQ * 128; i += 256) {
        int jj = i & 127;
        int rest = i >> 7;              // 0..39
        int kq = rest % NSQ;
        int r2 = (rest / NSQ) & 1;
        int cc = rest / (2 * NSQ);
        ws4[i] = *(const float4*)(w_hh + (size_t)((r2 << 7) + jj) * 256
                                       + (cc << 7) + 4 * NRQ + (kq << 2));
    }

    // --- register weights: rows j and j+128, k-quads 0..NRQ-1 of window
    unsigned long long w0[2 * NRQ], w1[2 * NRQ];
    {
        const float4* p0 = (const float4*)(w_hh + (size_t)j * 256 + (c << 7));
        const float4* p1 = (const float4*)(w_hh + (size_t)(j + 128) * 256 + (c << 7));
#pragma unroll
        for (int q = 0; q < NRQ; q++) {
            float4 v0 = p0[q], v1 = p1[q];
            w0[2 * q]     = pack2(v0.x, v0.y);
            w0[2 * q + 1] = pack2(v0.z, v0.w);
            w1[2 * q]     = pack2(v1.x, v1.y);
            w1[2 * q + 1] = pack2(v1.z, v1.w);
        }
    }

    // zero initial h (both buffers incl. pads)
    h_buf[tid] = 0.0f;
    h_buf[256 + tid] = 0.0f;
    if (tid < 8) h_buf[512 + tid] = 0.0f;
    __syncthreads();

    const int myrow = c ? (j + 128) : j;       // row this thread finishes
    const int hoff  = c ? 132 : 0;             // padded read base (R11 FIX)
    // strength-reduced pointers (advance by fixed stride each step)
    const float* pre_ptr = g_pre + (size_t)d * (512 * 64 * 256)
                         + ((size_t)(d ? 511 : 0) * 64 + b) * 256 + myrow;
    const ptrdiff_t pre_stride = d ? -(ptrdiff_t)(64 * 256) : (ptrdiff_t)(64 * 256);
    float* out_ptr = out + (((size_t)b << 9) + (d ? 511 : 0)) * 512 + (d << 8) + myrow;
    const ptrdiff_t out_stride = d ? -(ptrdiff_t)512 : (ptrdiff_t)512;

    float pre_cur = *pre_ptr;
    pre_ptr += pre_stride;

    // streamed-weight bases for this thread (rows j, j+128; this c)
    const float4* ws_r0 = ws4 + ((c * 2 + 0) * NSQ) * 128 + j;
    const float4* ws_r1 = ws4 + ((c * 2 + 1) * NSQ) * 128 + j;

    for (int s = 0; s < 512; s++) {
        const int cur = s & 1, nxt = cur ^ 1;

        // prefetch next pre (in flight across the whole MAC)
        float pre_nxt = 0.0f;
        if (s < 511) { pre_nxt = *pre_ptr; pre_ptr += pre_stride; }

        const ulonglong2* hb = (const ulonglong2*)(h_buf + cur * 260 + hoff);

        // 4 independent accumulator chains
        unsigned long long a0e = 0ull, a0o = 0ull, a1e = 0ull, a1o = 0ull;

        // streamed-weight part first: fixed-address LDS issue early
#pragma unroll
        for (int kq = 0; kq < NSQ; kq++) {
            ulonglong2 h2  = hb[NRQ + kq];
            ulonglong2 wv0 = *(const ulonglong2*)&ws_r0[kq * 128];
            ulonglong2 wv1 = *(const ulonglong2*)&ws_r1[kq * 128];
            a0e = ffma2(wv0.x, h2.x, a0e);
            a0o = ffma2(wv0.y, h2.y, a0o);
            a1e = ffma2(wv1.x, h2.x, a1e);
            a1o = ffma2(wv1.y, h2.y, a1o);
        }
        // register-weight part
#pragma unroll
        for (int q = 0; q < NRQ; q++) {
            ulonglong2 h2 = hb[q];
            a0e = ffma2(w0[2 * q],     h2.x, a0e);
            a0o = ffma2(w0[2 * q + 1], h2.y, a0o);
            a1e = ffma2(w1[2 * q],     h2.x, a1e);
            a1o = ffma2(w1[2 * q + 1], h2.y, a1o);
        }
        float p0 = sum2(a0e) + sum2(a0o);   // partial row j     (this k-half)
        float p1 = sum2(a1e) + sum2(a1o);   // partial row j+128 (this k-half)

        if (c == 0) redB[j] = p1; else redA[j] = p0;
        __syncthreads();

        float v = c ? (p1 + redB[j]) : (p0 + redA[j]);
        float hv = fast_tanh(v + pre_cur);
        h_buf[nxt * 260 + (c ? (j + 132) : j)] = hv;
        *out_ptr = hv;
        out_ptr += out_stride;
        if (s == 511)
            out[OUT_YS + (((d << 6) + b) << 8) + myrow] = hv;
        pre_cur = pre_nxt;
        __syncthreads();   // publish h[nxt]; all reads of h[cur] done
    }
}

// ---------------------------------------------------------------------------
extern "C" void kernel_launch(void* const* d_in, const int* in_sizes, int n_in,
                              void* d_out, int out_size) {
    const float* x      = (const float*)d_in[0];
    const float* w_ih_f = (const float*)d_in[1];
    const float* w_hh_f = (const float*)d_in[2];
    const float* b_ih_f = (const float*)d_in[3];
    const float* b_hh_f = (const float*)d_in[4];
    const float* w_ih_b = (const float*)d_in[5];
    const float* w_hh_b = (const float*)d_in[6];
    const float* b_ih_b = (const float*)d_in[7];
    const float* b_hh_b = (const float*)d_in[8];
    float* out = (float*)d_out;

    pre_gemm_kernel<<<4096, 256>>>(x, w_ih_f, b_ih_f, b_hh_f,
                                   w_ih_b, b_ih_b, b_hh_b);

    static bool attr_set = false;
    if (!attr_set) {
        cudaFuncSetAttribute(rnn_step_kernel,
                             cudaFuncAttributeMaxDynamicSharedMemorySize, STEP_SMEM);
        attr_set = true;
    }
    rnn_step_kernel<<<128, 256, STEP_SMEM>>>(w_hh_f, w_hh_b, out);
}

// round 12
// speedup vs baseline: 1.3791x; 1.3791x over previous
#include <cuda_runtime.h>
#include <cuda_bf16.h>
#include <cstdint>

// TorchBiRNN: B=64, T=512, I=128, H=256 bidirectional tanh RNN.
// Phase 1: pre GEMM — single-shot staging: both k-stages loaded into 64KB
//          dynamic smem with one sync, then 32 k4 of FFMA2, occ 3.
// Phase 2: recurrence — EXACT R7 kernel (best measured: step 408us).

#define OUT_YS (64 * 512 * 512)
#define GEMM_SMEM 65536
#define STEP_SMEM 68608   // ws4 65536 + h_buf 2048 + redA 512 + redB 512

__device__ float g_pre[2 * 512 * 64 * 256];   // 64 MB scratch (module-static)

// ---------------- helpers ----------------
__device__ __forceinline__ unsigned long long ffma2(unsigned long long a,
                                                    unsigned long long b,
                                                    unsigned long long c) {
    unsigned long long d;
    asm("fma.rn.f32x2 %0, %1, %2, %3;" : "=l"(d) : "l"(a), "l"(b), "l"(c));
    return d;
}
__device__ __forceinline__ unsigned long long pack2(float a, float b) {
    unsigned long long r;
    asm("mov.b64 %0, {%1, %2};" : "=l"(r) : "f"(a), "f"(b));
    return r;
}
__device__ __forceinline__ float sum2(unsigned long long v) {
    float2 f;
    asm("mov.b64 {%0, %1}, %2;" : "=f"(f.x), "=f"(f.y) : "l"(v));
    return f.x + f.y;
}
__device__ __forceinline__ float fast_tanh(float x) {
    float e = __expf(2.0f * x);
    return 1.0f - __fdividef(2.0f, e + 1.0f);
}

// ---------------------------------------------------------------------------
// Phase 1: GEMM. M=32768 (m = t*64+b), N=256, K=128 (both stages staged
// up-front). 64x64 tile, 256 threads, 4x4 microtile, FFMA2, XOR-swizzle.
// Dynamic smem: xs4 2048 float4 | ws4 2048 float4 = 65536 B -> occ 3.
// ---------------------------------------------------------------------------
__global__ __launch_bounds__(256) void pre_gemm_kernel(
    const float* __restrict__ x,
    const float* __restrict__ w_ih_f, const float* __restrict__ b_ih_f,
    const float* __restrict__ b_hh_f,
    const float* __restrict__ w_ih_b, const float* __restrict__ b_ih_b,
    const float* __restrict__ b_hh_b)
{
    extern __shared__ __align__(16) float4 smem4[];
    float4* xs4 = smem4;            // [2][64][16]
    float4* ws4 = smem4 + 2048;     // [2][64][16]

    const int bx = blockIdx.x;
    const int d  = bx >> 11;
    const int mt = (bx & 2047) >> 2;
    const int nt = bx & 3;
    const float* __restrict__ w_ih = d ? w_ih_b : w_ih_f;
    const float* __restrict__ bi   = d ? b_ih_b : b_ih_f;
    const float* __restrict__ bh   = d ? b_hh_b : b_hh_f;
    const int m0 = mt << 6, n0 = nt << 6;
    const int tid = threadIdx.x;
    const int tm = tid & 15, tn = tid >> 4;

    // stage BOTH k-halves up front: 16 LDG.128 in flight, one sync
#pragma unroll
    for (int st = 0; st < 2; st++) {
        const int ks = st << 6;
#pragma unroll
        for (int i = 0; i < 4; i++) {
            int idx = tid + (i << 8);
            int r = idx >> 4, c4 = idx & 15;
            int sw = c4 ^ ((r >> 2) & 7);
            int m = m0 + r;
            int t = m >> 6, bb = m & 63;
            xs4[st * 1024 + r * 16 + sw] =
                *(const float4*)(x + ((size_t)(bb << 9) + t) * 128 + ks + (c4 << 2));
            ws4[st * 1024 + r * 16 + sw] =
                *(const float4*)(w_ih + ((size_t)(n0 + r) << 7) + ks + (c4 << 2));
        }
    }
    __syncthreads();

    unsigned long long acc[4][4];
#pragma unroll
    for (int m = 0; m < 4; m++)
#pragma unroll
        for (int n = 0; n < 4; n++) acc[m][n] = 0ull;

#pragma unroll
    for (int st = 0; st < 2; st++) {
#pragma unroll
        for (int k4 = 0; k4 < 16; k4++) {
            ulonglong2 a2[4], b2[4];
#pragma unroll
            for (int m = 0; m < 4; m++)
                a2[m] = *(const ulonglong2*)&xs4[st * 1024 + ((tm << 2) + m) * 16
                                                 + (k4 ^ (tm & 7))];
#pragma unroll
            for (int n = 0; n < 4; n++)
                b2[n] = *(const ulonglong2*)&ws4[st * 1024 + ((tn << 2) + n) * 16
                                                 + (k4 ^ (tn & 7))];
#pragma unroll
            for (int m = 0; m < 4; m++)
#pragma unroll
                for (int n = 0; n < 4; n++) {
                    acc[m][n] = ffma2(a2[m].x, b2[n].x, acc[m][n]);
                    acc[m][n] = ffma2(a2[m].y, b2[n].y, acc[m][n]);
                }
        }
    }

    const int nbase = n0 + (tn << 2);
    float4 bi4 = *(const float4*)(bi + nbase);
    float4 bh4 = *(const float4*)(bh + nbase);
    float4 bias;
    bias.x = bi4.x + bh4.x; bias.y = bi4.y + bh4.y;
    bias.z = bi4.z + bh4.z; bias.w = bi4.w + bh4.w;

#pragma unroll
    for (int m = 0; m < 4; m++) {
        int mrow = m0 + (tm << 2) + m;
        float4 o;
        o.x = sum2(acc[m][0]) + bias.x;
        o.y = sum2(acc[m][1]) + bias.y;
        o.z = sum2(acc[m][2]) + bias.z;
        o.w = sum2(acc[m][3]) + bias.w;
        *(float4*)(g_pre + ((size_t)(d * 32768 + mrow)) * 256 + nbase) = o;
    }
}

// ---------------------------------------------------------------------------
// Phase 2: recurrence — EXACT R7 kernel (step 408us measured).
// Grid 128 (one CTA per (batch,dir)), 256 threads.
// Thread (j = tid&127, c = tid>>7): rows {j, j+128}, k in [128c, 128c+128).
//   k[0:96) of window: weights in registers (48 ull per row).
//   k[96:128): weights in smem (float4 ws4[c][r2][kq][j], 64KB).
// Dyn smem: ws4 64KB | h_buf 2x256 | redA 128 | redB 128 = 68608 B.
// ---------------------------------------------------------------------------
__global__ __launch_bounds__(256, 1)
void rnn_step_kernel(const float* __restrict__ w_hh_f,
                     const float* __restrict__ w_hh_b,
                     float* __restrict__ out)
{
    extern __shared__ __align__(16) char smem_raw[];
    float4* ws4   = (float4*)smem_raw;                    // [2][2][8][128]
    float*  h_buf = (float*)(smem_raw + 65536);           // [2][256]
    float*  redA  = h_buf + 512;                          // [128] c1 partials (row j)
    float*  redB  = redA + 128;                           // [128] c0 partials (row j+128)

    const int id  = blockIdx.x;
    const int d   = id >> 6;
    const int b   = id & 63;
    const int tid = threadIdx.x;
    const int j   = tid & 127;
    const int c   = tid >> 7;

    const float* __restrict__ w_hh = d ? w_hh_b : w_hh_f;

    // --- fill smem weights: ws4[((cc*2+r2)*8+kq)*128 + jj] = w[r2*128+jj][cc*128+96+4kq]
    for (int i = tid; i < 4096; i += 256) {
        int jj = i & 127, kq = (i >> 7) & 7, r2 = (i >> 10) & 1, cc = i >> 11;
        ws4[i] = *(const float4*)(w_hh + (size_t)((r2 << 7) + jj) * 256
                                       + (cc << 7) + 96 + (kq << 2));
    }

    // --- register weights: rows j and j+128, k in [128c, 128c+96)
    unsigned long long w0[48], w1[48];
    {
        const float4* p0 = (const float4*)(w_hh + (size_t)j * 256 + (c << 7));
        const float4* p1 = (const float4*)(w_hh + (size_t)(j + 128) * 256 + (c << 7));
#pragma unroll
        for (int q = 0; q < 24; q++) {
            float4 v0 = p0[q], v1 = p1[q];
            w0[2 * q]     = pack2(v0.x, v0.y);
            w0[2 * q + 1] = pack2(v0.z, v0.w);
            w1[2 * q]     = pack2(v1.x, v1.y);
            w1[2 * q + 1] = pack2(v1.z, v1.w);
        }
    }

    // zero initial h
    h_buf[tid] = 0.0f;          // buffer 0 = h_buf[0..255]
    __syncthreads();

    const float* pre_base = g_pre + (size_t)d * (512 * 64 * 256);
    const int myrow = c ? (j + 128) : j;     // row this thread finishes
    float pre_cur;
    {
        int t0 = d ? 511 : 0;
        pre_cur = pre_base[((size_t)t0 * 64 + b) * 256 + myrow];
    }

    const float4* ws_r0 = ws4 + ((c * 2 + 0) * 8) * 128 + j;
    const float4* ws_r1 = ws4 + ((c * 2 + 1) * 8) * 128 + j;

    for (int s = 0; s < 512; s++) {
        const int cur = s & 1, nxt = cur ^ 1;
        const int t = d ? (511 - s) : s;

        // prefetch next pre
        float pre_nxt = 0.0f;
        if (s < 511) {
            int t2 = d ? (510 - s) : (s + 1);
            pre_nxt = pre_base[((size_t)t2 * 64 + b) * 256 + myrow];
        }

        const ulonglong2* hb = (const ulonglong2*)(h_buf + (cur << 8) + (c << 7));

        unsigned long long a0 = 0ull, a1 = 0ull;
        // register-weight part: k-quads 0..23
#pragma unroll
        for (int q = 0; q < 24; q++) {
            ulonglong2 h2 = hb[q];
            a0 = ffma2(w0[2 * q],     h2.x, a0);
            a0 = ffma2(w0[2 * q + 1], h2.y, a0);
            a1 = ffma2(w1[2 * q],     h2.x, a1);
            a1 = ffma2(w1[2 * q + 1], h2.y, a1);
        }
        // smem-weight part: k-quads 24..31
#pragma unroll
        for (int kq = 0; kq < 8; kq++) {
            ulonglong2 h2 = hb[24 + kq];
            ulonglong2 wv0 = *(const ulonglong2*)&ws_r0[kq * 128];
            ulonglong2 wv1 = *(const ulonglong2*)&ws_r1[kq * 128];
            a0 = ffma2(wv0.x, h2.x, a0);
            a0 = ffma2(wv0.y, h2.y, a0);
            a1 = ffma2(wv1.x, h2.x, a1);
            a1 = ffma2(wv1.y, h2.y, a1);
        }
        float p0 = sum2(a0);       // partial for row j     (this c's k-window)
        float p1 = sum2(a1);       // partial for row j+128

        if (c == 0) redB[j] = p1; else redA[j] = p0;
        __syncthreads();

        float v = c ? (p1 + redB[j]) : (p0 + redA[j]);
        float hv = fast_tanh(v + pre_cur);
        h_buf[(nxt << 8) + myrow] = hv;
        out[(((size_t)b << 9) + t) * 512 + (d << 8) + myrow] = hv;
        if (s == 511)
            out[OUT_YS + (((d << 6) + b) << 8) + myrow] = hv;
        pre_cur = pre_nxt;
        __syncthreads();
    }
}

// ---------------------------------------------------------------------------
extern "C" void kernel_launch(void* const* d_in, const int* in_sizes, int n_in,
                              void* d_out, int out_size) {
    const float* x      = (const float*)d_in[0];
    const float* w_ih_f = (const float*)d_in[1];
    const float* w_hh_f = (const float*)d_in[2];
    const float* b_ih_f = (const float*)d_in[3];
    const float* b_hh_f = (const float*)d_in[4];
    const float* w_ih_b = (const float*)d_in[5];
    const float* w_hh_b = (const float*)d_in[6];
    const float* b_ih_b = (const float*)d_in[7];
    const float* b_hh_b = (const float*)d_in[8];
    float* out = (float*)d_out;

    cudaFuncSetAttribute(pre_gemm_kernel,
                         cudaFuncAttributeMaxDynamicSharedMemorySize, GEMM_SMEM);
    cudaFuncSetAttribute(rnn_step_kernel,
                         cudaFuncAttributeMaxDynamicSharedMemorySize, STEP_SMEM);

    pre_gemm_kernel<<<4096, 256, GEMM_SMEM>>>(x, w_ih_f, b_ih_f, b_hh_f,
                                              w_ih_b, b_ih_b, b_hh_b);
    rnn_step_kernel<<<128, 256, STEP_SMEM>>>(w_hh_f, w_hh_b, out);
}

// round 13
// speedup vs baseline: 1.4585x; 1.0575x over previous
#include <cuda_runtime.h>
#include <cuda_bf16.h>
#include <cstdint>

// TorchBiRNN: B=64, T=512, I=128, H=256 bidirectional tanh RNN.
// Phase 1: pre GEMM v2 — 128x128 block tile, 8x8 microtile (halves smem
//          crossbar traffic vs 4x4), K=128 single-shot in 128KB smem.
// Phase 2: recurrence — EXACT R7/R12 kernel (best measured: step 406us).

#define OUT_YS (64 * 512 * 512)
#define GEMM_SMEM 131072
#define STEP_SMEM 68608   // ws4 65536 + h_buf 2048 + redA 512 + redB 512

__device__ float g_pre[2 * 512 * 64 * 256];   // 64 MB scratch (module-static)

// ---------------- helpers ----------------
__device__ __forceinline__ unsigned long long ffma2(unsigned long long a,
                                                    unsigned long long b,
                                                    unsigned long long c) {
    unsigned long long d;
    asm("fma.rn.f32x2 %0, %1, %2, %3;" : "=l"(d) : "l"(a), "l"(b), "l"(c));
    return d;
}
__device__ __forceinline__ unsigned long long pack2(float a, float b) {
    unsigned long long r;
    asm("mov.b64 %0, {%1, %2};" : "=l"(r) : "f"(a), "f"(b));
    return r;
}
__device__ __forceinline__ float sum2(unsigned long long v) {
    float2 f;
    asm("mov.b64 {%0, %1}, %2;" : "=f"(f.x), "=f"(f.y) : "l"(v));
    return f.x + f.y;
}
__device__ __forceinline__ float fast_tanh(float x) {
    float e = __expf(2.0f * x);
    return 1.0f - __fdividef(2.0f, e + 1.0f);
}

// ---------------------------------------------------------------------------
// Phase 1: GEMM v2. M=32768 (m = t*64+b), N=256, K=128.
// Block: 128(m) x 128(n), K=128 single-shot. 256 threads = 16(tm) x 16(tn),
// each computes 8x8. a-tile & b-tile: [row][kf4 0..31] float4, swizzle
// sw = kf4 ^ ((row>>3)&7)  (reads: rows 8*tm+mi -> 8 distinct groups across
// tm; b reads are half-warp broadcasts). Dyn smem 131072 B, occ 1.
// Grid: d (2) x mt (256) x nt (2) = 1024 blocks.
// ---------------------------------------------------------------------------
__global__ __launch_bounds__(256) void pre_gemm_kernel(
    const float* __restrict__ x,
    const float* __restrict__ w_ih_f, const float* __restrict__ b_ih_f,
    const float* __restrict__ b_hh_f,
    const float* __restrict__ w_ih_b, const float* __restrict__ b_ih_b,
    const float* __restrict__ b_hh_b)
{
    extern __shared__ __align__(16) float4 smem4[];
    float4* xs4 = smem4;            // [128][32]
    float4* ws4 = smem4 + 4096;     // [128][32]

    const int bx = blockIdx.x;
    const int d  = bx >> 9;
    const int r9 = bx & 511;
    const int mt = r9 >> 1;                 // 0..255
    const int nt = r9 & 1;                  // 0..1
    const float* __restrict__ w_ih = d ? w_ih_b : w_ih_f;
    const float* __restrict__ bi   = d ? b_ih_b : b_ih_f;
    const float* __restrict__ bh   = d ? b_hh_b : b_hh_f;
    const int m0 = mt << 7, n0 = nt << 7;
    const int tid = threadIdx.x;
    const int tm = tid & 15, tn = tid >> 4;

    // stage full K for both tiles: 16+16 LDG.128 per thread, one sync
#pragma unroll
    for (int i = 0; i < 16; i++) {
        int idx = tid + (i << 8);           // 0..4095
        int r = idx >> 5, kf4 = idx & 31;
        int sw = kf4 ^ ((r >> 3) & 7);
        int m = m0 + r;
        int t = m >> 6, bb = m & 63;
        xs4[(r << 5) + sw] =
            *(const float4*)(x + ((size_t)(bb << 9) + t) * 128 + (kf4 << 2));
        ws4[(r << 5) + sw] =
            *(const float4*)(w_ih + ((size_t)(n0 + r) << 7) + (kf4 << 2));
    }
    __syncthreads();

    unsigned long long acc[8][8];
#pragma unroll
    for (int m = 0; m < 8; m++)
#pragma unroll
        for (int n = 0; n < 8; n++) acc[m][n] = 0ull;

#pragma unroll
    for (int k4 = 0; k4 < 32; k4++) {
        ulonglong2 a2[8], b2[8];
#pragma unroll
        for (int m = 0; m < 8; m++)
            a2[m] = *(const ulonglong2*)&xs4[(((tm << 3) + m) << 5) + (k4 ^ (tm & 7))];
#pragma unroll
        for (int n = 0; n < 8; n++)
            b2[n] = *(const ulonglong2*)&ws4[(((tn << 3) + n) << 5) + (k4 ^ (tn & 7))];
#pragma unroll
        for (int m = 0; m < 8; m++)
#pragma unroll
            for (int n = 0; n < 8; n++) {
                acc[m][n] = ffma2(a2[m].x, b2[n].x, acc[m][n]);
                acc[m][n] = ffma2(a2[m].y, b2[n].y, acc[m][n]);
            }
    }

    const int nbase = n0 + (tn << 3);
    float4 biL = *(const float4*)(bi + nbase);
    float4 biH = *(const float4*)(bi + nbase + 4);
    float4 bhL = *(const float4*)(bh + nbase);
    float4 bhH = *(const float4*)(bh + nbase + 4);
    float4 bL, bH;
    bL.x = biL.x + bhL.x; bL.y = biL.y + bhL.y;
    bL.z = biL.z + bhL.z; bL.w = biL.w + bhL.w;
    bH.x = biH.x + bhH.x; bH.y = biH.y + bhH.y;
    bH.z = biH.z + bhH.z; bH.w = biH.w + bhH.w;

#pragma unroll
    for (int m = 0; m < 8; m++) {
        int mrow = m0 + (tm << 3) + m;
        float* op = g_pre + ((size_t)(d * 32768 + mrow)) * 256 + nbase;
        float4 oL, oH;
        oL.x = sum2(acc[m][0]) + bL.x;
        oL.y = sum2(acc[m][1]) + bL.y;
        oL.z = sum2(acc[m][2]) + bL.z;
        oL.w = sum2(acc[m][3]) + bL.w;
        oH.x = sum2(acc[m][4]) + bH.x;
        oH.y = sum2(acc[m][5]) + bH.y;
        oH.z = sum2(acc[m][6]) + bH.z;
        oH.w = sum2(acc[m][7]) + bH.w;
        *(float4*)op = oL;
        *(float4*)(op + 4) = oH;
    }
}

// ---------------------------------------------------------------------------
// Phase 2: recurrence — EXACT R7/R12 kernel (step 406us measured).
// Grid 128 (one CTA per (batch,dir)), 256 threads.
// Thread (j = tid&127, c = tid>>7): rows {j, j+128}, k in [128c, 128c+128).
//   k[0:96) of window: weights in registers (48 ull per row).
//   k[96:128): weights in smem (float4 ws4[c][r2][kq][j], 64KB).
// Dyn smem: ws4 64KB | h_buf 2x256 | redA 128 | redB 128 = 68608 B.
// ---------------------------------------------------------------------------
__global__ __launch_bounds__(256, 1)
void rnn_step_kernel(const float* __restrict__ w_hh_f,
                     const float* __restrict__ w_hh_b,
                     float* __restrict__ out)
{
    extern __shared__ __align__(16) char smem_raw[];
    float4* ws4   = (float4*)smem_raw;                    // [2][2][8][128]
    float*  h_buf = (float*)(smem_raw + 65536);           // [2][256]
    float*  redA  = h_buf + 512;                          // [128] c1 partials (row j)
    float*  redB  = redA + 128;                           // [128] c0 partials (row j+128)

    const int id  = blockIdx.x;
    const int d   = id >> 6;
    const int b   = id & 63;
    const int tid = threadIdx.x;
    const int j   = tid & 127;
    const int c   = tid >> 7;

    const float* __restrict__ w_hh = d ? w_hh_b : w_hh_f;

    // --- fill smem weights: ws4[((cc*2+r2)*8+kq)*128 + jj] = w[r2*128+jj][cc*128+96+4kq]
    for (int i = tid; i < 4096; i += 256) {
        int jj = i & 127, kq = (i >> 7) & 7, r2 = (i >> 10) & 1, cc = i >> 11;
        ws4[i] = *(const float4*)(w_hh + (size_t)((r2 << 7) + jj) * 256
                                       + (cc << 7) + 96 + (kq << 2));
    }

    // --- register weights: rows j and j+128, k in [128c, 128c+96)
    unsigned long long w0[48], w1[48];
    {
        const float4* p0 = (const float4*)(w_hh + (size_t)j * 256 + (c << 7));
        const float4* p1 = (const float4*)(w_hh + (size_t)(j + 128) * 256 + (c << 7));
#pragma unroll
        for (int q = 0; q < 24; q++) {
            float4 v0 = p0[q], v1 = p1[q];
            w0[2 * q]     = pack2(v0.x, v0.y);
            w0[2 * q + 1] = pack2(v0.z, v0.w);
            w1[2 * q]     = pack2(v1.x, v1.y);
            w1[2 * q + 1] = pack2(v1.z, v1.w);
        }
    }

    // zero initial h
    h_buf[tid] = 0.0f;          // buffer 0 = h_buf[0..255]
    __syncthreads();

    const float* pre_base = g_pre + (size_t)d * (512 * 64 * 256);
    const int myrow = c ? (j + 128) : j;     // row this thread finishes
    float pre_cur;
    {
        int t0 = d ? 511 : 0;
        pre_cur = pre_base[((size_t)t0 * 64 + b) * 256 + myrow];
    }

    const float4* ws_r0 = ws4 + ((c * 2 + 0) * 8) * 128 + j;
    const float4* ws_r1 = ws4 + ((c * 2 + 1) * 8) * 128 + j;

    for (int s = 0; s < 512; s++) {
        const int cur = s & 1, nxt = cur ^ 1;
        const int t = d ? (511 - s) : s;

        // prefetch next pre
        float pre_nxt = 0.0f;
        if (s < 511) {
            int t2 = d ? (510 - s) : (s + 1);
            pre_nxt = pre_base[((size_t)t2 * 64 + b) * 256 + myrow];
        }

        const ulonglong2* hb = (const ulonglong2*)(h_buf + (cur << 8) + (c << 7));

        unsigned long long a0 = 0ull, a1 = 0ull;
        // register-weight part: k-quads 0..23
#pragma unroll
        for (int q = 0; q < 24; q++) {
            ulonglong2 h2 = hb[q];
            a0 = ffma2(w0[2 * q],     h2.x, a0);
            a0 = ffma2(w0[2 * q + 1], h2.y, a0);
            a1 = ffma2(w1[2 * q],     h2.x, a1);
            a1 = ffma2(w1[2 * q + 1], h2.y, a1);
        }
        // smem-weight part: k-quads 24..31
#pragma unroll
        for (int kq = 0; kq < 8; kq++) {
            ulonglong2 h2 = hb[24 + kq];
            ulonglong2 wv0 = *(const ulonglong2*)&ws_r0[kq * 128];
            ulonglong2 wv1 = *(const ulonglong2*)&ws_r1[kq * 128];
            a0 = ffma2(wv0.x, h2.x, a0);
            a0 = ffma2(wv0.y, h2.y, a0);
            a1 = ffma2(wv1.x, h2.x, a1);
            a1 = ffma2(wv1.y, h2.y, a1);
        }
        float p0 = sum2(a0);       // partial for row j     (this c's k-window)
        float p1 = sum2(a1);       // partial for row j+128

        if (c == 0) redB[j] = p1; else redA[j] = p0;
        __syncthreads();

        float v = c ? (p1 + redB[j]) : (p0 + redA[j]);
        float hv = fast_tanh(v + pre_cur);
        h_buf[(nxt << 8) + myrow] = hv;
        out[(((size_t)b << 9) + t) * 512 + (d << 8) + myrow] = hv;
        if (s == 511)
            out[OUT_YS + (((d << 6) + b) << 8) + myrow] = hv;
        pre_cur = pre_nxt;
        __syncthreads();
    }
}

// ---------------------------------------------------------------------------
extern "C" void kernel_launch(void* const* d_in, const int* in_sizes, int n_in,
                              void* d_out, int out_size) {
    const float* x      = (const float*)d_in[0];
    const float* w_ih_f = (const float*)d_in[1];
    const float* w_hh_f = (const float*)d_in[2];
    const float* b_ih_f = (const float*)d_in[3];
    const float* b_hh_f = (const float*)d_in[4];
    const float* w_ih_b = (const float*)d_in[5];
    const float* w_hh_b = (const float*)d_in[6];
    const float* b_ih_b = (const float*)d_in[7];
    const float* b_hh_b = (const float*)d_in[8];
    float* out = (float*)d_out;

    cudaFuncSetAttribute(pre_gemm_kernel,
                         cudaFuncAttributeMaxDynamicSharedMemorySize, GEMM_SMEM);
    cudaFuncSetAttribute(rnn_step_kernel,
                         cudaFuncAttributeMaxDynamicSharedMemorySize, STEP_SMEM);

    pre_gemm_kernel<<<1024, 256, GEMM_SMEM>>>(x, w_ih_f, b_ih_f, b_hh_f,
                                              w_ih_b, b_ih_b, b_hh_b);
    rnn_step_kernel<<<128, 256, STEP_SMEM>>>(w_hh_f, w_hh_b, out);
}

// round 14
// speedup vs baseline: 1.4774x; 1.0130x over previous
#include <cuda_runtime.h>
#include <cuda_bf16.h>
#include <cstdint>

// TorchBiRNN: B=64, T=512, I=128, H=256 bidirectional tanh RNN.
// Phase 1: pre GEMM v4 — 128x128 tile, 8x8 microtile, K in 4 chunks of 32
//          loaded via cp.async (2-deep pipeline) so the L2-BW-bound fill
//          overlaps the MAC. Phase 2: EXACT R7 step kernel (407us).

#define OUT_YS (64 * 512 * 512)
#define GEMM_SMEM 131072
#define STEP_SMEM 68608   // ws4 65536 + h_buf 2048 + redA 512 + redB 512

__device__ float g_pre[2 * 512 * 64 * 256];   // 64 MB scratch (module-static)

// ---------------- helpers ----------------
__device__ __forceinline__ unsigned long long ffma2(unsigned long long a,
                                                    unsigned long long b,
                                                    unsigned long long c) {
    unsigned long long d;
    asm("fma.rn.f32x2 %0, %1, %2, %3;" : "=l"(d) : "l"(a), "l"(b), "l"(c));
    return d;
}
__device__ __forceinline__ unsigned long long pack2(float a, float b) {
    unsigned long long r;
    asm("mov.b64 %0, {%1, %2};" : "=l"(r) : "f"(a), "f"(b));
    return r;
}
__device__ __forceinline__ float sum2(unsigned long long v) {
    float2 f;
    asm("mov.b64 {%0, %1}, %2;" : "=f"(f.x), "=f"(f.y) : "l"(v));
    return f.x + f.y;
}
__device__ __forceinline__ float fast_tanh(float x) {
    float e = __expf(2.0f * x);
    return 1.0f - __fdividef(2.0f, e + 1.0f);
}
__device__ __forceinline__ uint32_t s2u32(const void* p) {
    return (uint32_t)__cvta_generic_to_shared((void*)p);
}
__device__ __forceinline__ void cp_async16(uint32_t dst, const void* src) {
    asm volatile("cp.async.cg.shared.global [%0], [%1], 16;"
                 :: "r"(dst), "l"(src) : "memory");
}
#define CP_COMMIT() asm volatile("cp.async.commit_group;" ::: "memory")
#define CP_WAIT(n)  asm volatile("cp.async.wait_group %0;" :: "n"(n) : "memory")

// ---------------------------------------------------------------------------
// Phase 1: GEMM v4. M=32768 (m = t*64+b), N=256, K=128.
// Block 128(m) x 128(n); 256 thr = 16(tm) x 16(tn); 8x8 microtile.
// K chunks of 32 (8 f4/row), each chunk: xs4/ws4 [128][8] f4, swizzle
// sw = kf4 ^ ((r>>3)&7). cp.async 2-deep pipeline over 4 chunks.
// Dyn smem: 4 ch x 1024 f4 x 2 tiles x 16B = 131072 B. Grid 1024.
// ---------------------------------------------------------------------------
__global__ __launch_bounds__(256) void pre_gemm_kernel(
    const float* __restrict__ x,
    const float* __restrict__ w_ih_f, const float* __restrict__ b_ih_f,
    const float* __restrict__ b_hh_f,
    const float* __restrict__ w_ih_b, const float* __restrict__ b_ih_b,
    const float* __restrict__ b_hh_b)
{
    extern __shared__ __align__(16) float4 smem4[];
    float4* xs4 = smem4;            // [4][128][8]
    float4* ws4 = smem4 + 4096;     // [4][128][8]

    const int bx = blockIdx.x;
    const int d  = bx >> 9;
    const int r9 = bx & 511;
    const int mt = r9 >> 1;                 // 0..255
    const int nt = r9 & 1;                  // 0..1
    const float* __restrict__ w_ih = d ? w_ih_b : w_ih_f;
    const float* __restrict__ bi   = d ? b_ih_b : b_ih_f;
    const float* __restrict__ bh   = d ? b_hh_b : b_hh_f;
    const int m0 = mt << 7, n0 = nt << 7;
    const int tid = threadIdx.x;
    const int tm = tid & 15, tn = tid >> 4;

    const uint32_t xs_u = s2u32(xs4);
    const uint32_t ws_u = s2u32(ws4);

    // chunk loader: 4 f4 per tile per thread
    auto load_chunk = [&](int ch) {
#pragma unroll
        for (int i = 0; i < 4; i++) {
            int idx = tid + (i << 8);         // 0..1023
            int r = idx >> 3, kf4 = idx & 7;
            int sw = kf4 ^ ((r >> 3) & 7);
            uint32_t off = (uint32_t)(ch * 1024 + (r << 3) + sw) << 4;
            int m = m0 + r;
            int t = m >> 6, bb = m & 63;
            cp_async16(xs_u + off,
                       x + ((size_t)(bb << 9) + t) * 128 + (ch << 5) + (kf4 << 2));
            cp_async16(ws_u + off,
                       w_ih + ((size_t)(n0 + r) << 7) + (ch << 5) + (kf4 << 2));
        }
        CP_COMMIT();
    };

    load_chunk(0);
    load_chunk(1);

    unsigned long long acc[8][8];
#pragma unroll
    for (int m = 0; m < 8; m++)
#pragma unroll
        for (int n = 0; n < 8; n++) acc[m][n] = 0ull;

#pragma unroll
    for (int ch = 0; ch < 4; ch++) {
        if (ch < 3) CP_WAIT(1); else CP_WAIT(0);
        __syncthreads();
        if (ch < 2) load_chunk(ch + 2);

#pragma unroll
        for (int k4 = 0; k4 < 8; k4++) {
            ulonglong2 a2[8], b2[8];
#pragma unroll
            for (int m = 0; m < 8; m++)
                a2[m] = *(const ulonglong2*)&xs4[ch * 1024 + (((tm << 3) + m) << 3)
                                                 + (k4 ^ (tm & 7))];
#pragma unroll
            for (int n = 0; n < 8; n++)
                b2[n] = *(const ulonglong2*)&ws4[ch * 1024 + (((tn << 3) + n) << 3)
                                                 + (k4 ^ (tn & 7))];
#pragma unroll
            for (int m = 0; m < 8; m++)
#pragma unroll
                for (int n = 0; n < 8; n++) {
                    acc[m][n] = ffma2(a2[m].x, b2[n].x, acc[m][n]);
                    acc[m][n] = ffma2(a2[m].y, b2[n].y, acc[m][n]);
                }
        }
    }

    const int nbase = n0 + (tn << 3);
    float4 biL = *(const float4*)(bi + nbase);
    float4 biH = *(const float4*)(bi + nbase + 4);
    float4 bhL = *(const float4*)(bh + nbase);
    float4 bhH = *(const float4*)(bh + nbase + 4);
    float4 bL, bH;
    bL.x = biL.x + bhL.x; bL.y = biL.y + bhL.y;
    bL.z = biL.z + bhL.z; bL.w = biL.w + bhL.w;
    bH.x = biH.x + bhH.x; bH.y = biH.y + bhH.y;
    bH.z = biH.z + bhH.z; bH.w = biH.w + bhH.w;

#pragma unroll
    for (int m = 0; m < 8; m++) {
        int mrow = m0 + (tm << 3) + m;
        float* op = g_pre + ((size_t)(d * 32768 + mrow)) * 256 + nbase;
        float4 oL, oH;
        oL.x = sum2(acc[m][0]) + bL.x;
        oL.y = sum2(acc[m][1]) + bL.y;
        oL.z = sum2(acc[m][2]) + bL.z;
        oL.w = sum2(acc[m][3]) + bL.w;
        oH.x = sum2(acc[m][4]) + bH.x;
        oH.y = sum2(acc[m][5]) + bH.y;
        oH.z = sum2(acc[m][6]) + bH.z;
        oH.w = sum2(acc[m][7]) + bH.w;
        *(float4*)op = oL;
        *(float4*)(op + 4) = oH;
    }
}

// ---------------------------------------------------------------------------
// Phase 2: recurrence — EXACT R7/R12/R13 kernel (step 406-407us measured).
// Grid 128 (one CTA per (batch,dir)), 256 threads.
// Thread (j = tid&127, c = tid>>7): rows {j, j+128}, k in [128c, 128c+128).
//   k[0:96) of window: weights in registers (48 ull per row).
//   k[96:128): weights in smem (float4 ws4[c][r2][kq][j], 64KB).
// Dyn smem: ws4 64KB | h_buf 2x256 | redA 128 | redB 128 = 68608 B.
// ---------------------------------------------------------------------------
__global__ __launch_bounds__(256, 1)
void rnn_step_kernel(const float* __restrict__ w_hh_f,
                     const float* __restrict__ w_hh_b,
                     float* __restrict__ out)
{
    extern __shared__ __align__(16) char smem_raw[];
    float4* ws4   = (float4*)smem_raw;                    // [2][2][8][128]
    float*  h_buf = (float*)(smem_raw + 65536);           // [2][256]
    float*  redA  = h_buf + 512;                          // [128] c1 partials (row j)
    float*  redB  = redA + 128;                           // [128] c0 partials (row j+128)

    const int id  = blockIdx.x;
    const int d   = id >> 6;
    const int b   = id & 63;
    const int tid = threadIdx.x;
    const int j   = tid & 127;
    const int c   = tid >> 7;

    const float* __restrict__ w_hh = d ? w_hh_b : w_hh_f;

    // --- fill smem weights: ws4[((cc*2+r2)*8+kq)*128 + jj] = w[r2*128+jj][cc*128+96+4kq]
    for (int i = tid; i < 4096; i += 256) {
        int jj = i & 127, kq = (i >> 7) & 7, r2 = (i >> 10) & 1, cc = i >> 11;
        ws4[i] = *(const float4*)(w_hh + (size_t)((r2 << 7) + jj) * 256
                                       + (cc << 7) + 96 + (kq << 2));
    }

    // --- register weights: rows j and j+128, k in [128c, 128c+96)
    unsigned long long w0[48], w1[48];
    {
        const float4* p0 = (const float4*)(w_hh + (size_t)j * 256 + (c << 7));
        const float4* p1 = (const float4*)(w_hh + (size_t)(j + 128) * 256 + (c << 7));
#pragma unroll
        for (int q = 0; q < 24; q++) {
            float4 v0 = p0[q], v1 = p1[q];
            w0[2 * q]     = pack2(v0.x, v0.y);
            w0[2 * q + 1] = pack2(v0.z, v0.w);
            w1[2 * q]     = pack2(v1.x, v1.y);
            w1[2 * q + 1] = pack2(v1.z, v1.w);
        }
    }

    // zero initial h
    h_buf[tid] = 0.0f;          // buffer 0 = h_buf[0..255]
    __syncthreads();

    const float* pre_base = g_pre + (size_t)d * (512 * 64 * 256);
    const int myrow = c ? (j + 128) : j;     // row this thread finishes
    float pre_cur;
    {
        int t0 = d ? 511 : 0;
        pre_cur = pre_base[((size_t)t0 * 64 + b) * 256 + myrow];
    }

    const float4* ws_r0 = ws4 + ((c * 2 + 0) * 8) * 128 + j;
    const float4* ws_r1 = ws4 + ((c * 2 + 1) * 8) * 128 + j;

    for (int s = 0; s < 512; s++) {
        const int cur = s & 1, nxt = cur ^ 1;
        const int t = d ? (511 - s) : s;

        // prefetch next pre
        float pre_nxt = 0.0f;
        if (s < 511) {
            int t2 = d ? (510 - s) : (s + 1);
            pre_nxt = pre_base[((size_t)t2 * 64 + b) * 256 + myrow];
        }

        const ulonglong2* hb = (const ulonglong2*)(h_buf + (cur << 8) + (c << 7));

        unsigned long long a0 = 0ull, a1 = 0ull;
        // register-weight part: k-quads 0..23
#pragma unroll
        for (int q = 0; q < 24; q++) {
            ulonglong2 h2 = hb[q];
            a0 = ffma2(w0[2 * q],     h2.x, a0);
            a0 = ffma2(w0[2 * q + 1], h2.y, a0);
            a1 = ffma2(w1[2 * q],     h2.x, a1);
            a1 = ffma2(w1[2 * q + 1], h2.y, a1);
        }
        // smem-weight part: k-quads 24..31
#pragma unroll
        for (int kq = 0; kq < 8; kq++) {
            ulonglong2 h2 = hb[24 + kq];
            ulonglong2 wv0 = *(const ulonglong2*)&ws_r0[kq * 128];
            ulonglong2 wv1 = *(const ulonglong2*)&ws_r1[kq * 128];
            a0 = ffma2(wv0.x, h2.x, a0);
            a0 = ffma2(wv0.y, h2.y, a0);
            a1 = ffma2(wv1.x, h2.x, a1);
            a1 = ffma2(wv1.y, h2.y, a1);
        }
        float p0 = sum2(a0);       // partial for row j     (this c's k-window)
        float p1 = sum2(a1);       // partial for row j+128

        if (c == 0) redB[j] = p1; else redA[j] = p0;
        __syncthreads();

        float v = c ? (p1 + redB[j]) : (p0 + redA[j]);
        float hv = fast_tanh(v + pre_cur);
        h_buf[(nxt << 8) + myrow] = hv;
        out[(((size_t)b << 9) + t) * 512 + (d << 8) + myrow] = hv;
        if (s == 511)
            out[OUT_YS + (((d << 6) + b) << 8) + myrow] = hv;
        pre_cur = pre_nxt;
        __syncthreads();
    }
}

// ---------------------------------------------------------------------------
extern "C" void kernel_launch(void* const* d_in, const int* in_sizes, int n_in,
                              void* d_out, int out_size) {
    const float* x      = (const float*)d_in[0];
    const float* w_ih_f = (const float*)d_in[1];
    const float* w_hh_f = (const float*)d_in[2];
    const float* b_ih_f = (const float*)d_in[3];
    const float* b_hh_f = (const float*)d_in[4];
    const float* w_ih_b = (const float*)d_in[5];
    const float* w_hh_b = (const float*)d_in[6];
    const float* b_ih_b = (const float*)d_in[7];
    const float* b_hh_b = (const float*)d_in[8];
    float* out = (float*)d_out;

    cudaFuncSetAttribute(pre_gemm_kernel,
                         cudaFuncAttributeMaxDynamicSharedMemorySize, GEMM_SMEM);
    cudaFuncSetAttribute(rnn_step_kernel,
                         cudaFuncAttributeMaxDynamicSharedMemorySize, STEP_SMEM);

    pre_gemm_kernel<<<1024, 256, GEMM_SMEM>>>(x, w_ih_f, b_ih_f, b_hh_f,
                                              w_ih_b, b_ih_b, b_hh_b);
    rnn_step_kernel<<<128, 256, STEP_SMEM>>>(w_hh_f, w_hh_b, out);
}

// round 15
// speedup vs baseline: 1.4982x; 1.0141x over previous
#include <cuda_runtime.h>
#include <cuda_bf16.h>
#include <cuda_fp16.h>
#include <cstdint>

// TorchBiRNN: B=64, T=512, I=128, H=256 bidirectional tanh RNN.
// Phase 1: pre GEMM v4 (R14): 128x128 tile, 8x8 microtile, cp.async pipeline.
// Phase 2: R7 step kernel with the streamed w_hh quarter stored as fp16
//          (32KB smem, half the weight LDS instructions & wavefronts).

#define OUT_YS (64 * 512 * 512)
#define GEMM_SMEM 131072
#define STEP_SMEM (32768 + 2048 + 512 + 512)   // wsh fp16 + h_buf + redA + redB

__device__ float g_pre[2 * 512 * 64 * 256];   // 64 MB scratch (module-static)

// ---------------- helpers ----------------
__device__ __forceinline__ unsigned long long ffma2(unsigned long long a,
                                                    unsigned long long b,
                                                    unsigned long long c) {
    unsigned long long d;
    asm("fma.rn.f32x2 %0, %1, %2, %3;" : "=l"(d) : "l"(a), "l"(b), "l"(c));
    return d;
}
__device__ __forceinline__ unsigned long long pack2(float a, float b) {
    unsigned long long r;
    asm("mov.b64 %0, {%1, %2};" : "=l"(r) : "f"(a), "f"(b));
    return r;
}
__device__ __forceinline__ float sum2(unsigned long long v) {
    float2 f;
    asm("mov.b64 {%0, %1}, %2;" : "=f"(f.x), "=f"(f.y) : "l"(v));
    return f.x + f.y;
}
__device__ __forceinline__ float fast_tanh(float x) {
    float e = __expf(2.0f * x);
    return 1.0f - __fdividef(2.0f, e + 1.0f);
}
// half2 bits -> packed float2 (ull) for ffma2
__device__ __forceinline__ unsigned long long h2f2(uint32_t h) {
    __half2 hh = *reinterpret_cast<__half2*>(&h);
    float2 f = __half22float2(hh);
    return pack2(f.x, f.y);
}
__device__ __forceinline__ uint32_t f2h2(float a, float b) {
    __half2 v = __floats2half2_rn(a, b);
    return *reinterpret_cast<uint32_t*>(&v);
}
__device__ __forceinline__ uint32_t s2u32(const void* p) {
    return (uint32_t)__cvta_generic_to_shared((void*)p);
}
__device__ __forceinline__ void cp_async16(uint32_t dst, const void* src) {
    asm volatile("cp.async.cg.shared.global [%0], [%1], 16;"
                 :: "r"(dst), "l"(src) : "memory");
}
#define CP_COMMIT() asm volatile("cp.async.commit_group;" ::: "memory")
#define CP_WAIT(n)  asm volatile("cp.async.wait_group %0;" :: "n"(n) : "memory")

// ---------------------------------------------------------------------------
// Phase 1: GEMM v4 (unchanged from R14). 128x128 tile, 8x8 microtile,
// K in 4 chunks of 32 via cp.async 2-deep pipeline. Grid 1024, occ 1.
// ---------------------------------------------------------------------------
__global__ __launch_bounds__(256) void pre_gemm_kernel(
    const float* __restrict__ x,
    const float* __restrict__ w_ih_f, const float* __restrict__ b_ih_f,
    const float* __restrict__ b_hh_f,
    const float* __restrict__ w_ih_b, const float* __restrict__ b_ih_b,
    const float* __restrict__ b_hh_b)
{
    extern __shared__ __align__(16) float4 smem4[];
    float4* xs4 = smem4;            // [4][128][8]
    float4* ws4 = smem4 + 4096;     // [4][128][8]

    const int bx = blockIdx.x;
    const int d  = bx >> 9;
    const int r9 = bx & 511;
    const int mt = r9 >> 1;
    const int nt = r9 & 1;
    const float* __restrict__ w_ih = d ? w_ih_b : w_ih_f;
    const float* __restrict__ bi   = d ? b_ih_b : b_ih_f;
    const float* __restrict__ bh   = d ? b_hh_b : b_hh_f;
    const int m0 = mt << 7, n0 = nt << 7;
    const int tid = threadIdx.x;
    const int tm = tid & 15, tn = tid >> 4;

    const uint32_t xs_u = s2u32(xs4);
    const uint32_t ws_u = s2u32(ws4);

    auto load_chunk = [&](int ch) {
#pragma unroll
        for (int i = 0; i < 4; i++) {
            int idx = tid + (i << 8);
            int r = idx >> 3, kf4 = idx & 7;
            int sw = kf4 ^ ((r >> 3) & 7);
            uint32_t off = (uint32_t)(ch * 1024 + (r << 3) + sw) << 4;
            int m = m0 + r;
            int t = m >> 6, bb = m & 63;
            cp_async16(xs_u + off,
                       x + ((size_t)(bb << 9) + t) * 128 + (ch << 5) + (kf4 << 2));
            cp_async16(ws_u + off,
                       w_ih + ((size_t)(n0 + r) << 7) + (ch << 5) + (kf4 << 2));
        }
        CP_COMMIT();
    };

    load_chunk(0);
    load_chunk(1);

    unsigned long long acc[8][8];
#pragma unroll
    for (int m = 0; m < 8; m++)
#pragma unroll
        for (int n = 0; n < 8; n++) acc[m][n] = 0ull;

#pragma unroll
    for (int ch = 0; ch < 4; ch++) {
        if (ch < 3) CP_WAIT(1); else CP_WAIT(0);
        __syncthreads();
        if (ch < 2) load_chunk(ch + 2);

#pragma unroll
        for (int k4 = 0; k4 < 8; k4++) {
            ulonglong2 a2[8], b2[8];
#pragma unroll
            for (int m = 0; m < 8; m++)
                a2[m] = *(const ulonglong2*)&xs4[ch * 1024 + (((tm << 3) + m) << 3)
                                                 + (k4 ^ (tm & 7))];
#pragma unroll
            for (int n = 0; n < 8; n++)
                b2[n] = *(const ulonglong2*)&ws4[ch * 1024 + (((tn << 3) + n) << 3)
                                                 + (k4 ^ (tn & 7))];
#pragma unroll
            for (int m = 0; m < 8; m++)
#pragma unroll
                for (int n = 0; n < 8; n++) {
                    acc[m][n] = ffma2(a2[m].x, b2[n].x, acc[m][n]);
                    acc[m][n] = ffma2(a2[m].y, b2[n].y, acc[m][n]);
                }
        }
    }

    const int nbase = n0 + (tn << 3);
    float4 biL = *(const float4*)(bi + nbase);
    float4 biH = *(const float4*)(bi + nbase + 4);
    float4 bhL = *(const float4*)(bh + nbase);
    float4 bhH = *(const float4*)(bh + nbase + 4);
    float4 bL, bH;
    bL.x = biL.x + bhL.x; bL.y = biL.y + bhL.y;
    bL.z = biL.z + bhL.z; bL.w = biL.w + bhL.w;
    bH.x = biH.x + bhH.x; bH.y = biH.y + bhH.y;
    bH.z = biH.z + bhH.z; bH.w = biH.w + bhH.w;

#pragma unroll
    for (int m = 0; m < 8; m++) {
        int mrow = m0 + (tm << 3) + m;
        float* op = g_pre + ((size_t)(d * 32768 + mrow)) * 256 + nbase;
        float4 oL, oH;
        oL.x = sum2(acc[m][0]) + bL.x;
        oL.y = sum2(acc[m][1]) + bL.y;
        oL.z = sum2(acc[m][2]) + bL.z;
        oL.w = sum2(acc[m][3]) + bL.w;
        oH.x = sum2(acc[m][4]) + bH.x;
        oH.y = sum2(acc[m][5]) + bH.y;
        oH.z = sum2(acc[m][6]) + bH.z;
        oH.w = sum2(acc[m][7]) + bH.w;
        *(float4*)op = oL;
        *(float4*)(op + 4) = oH;
    }
}

// ---------------------------------------------------------------------------
// Phase 2: recurrence. Grid 128 (one CTA per (batch,dir)), 256 threads.
// Thread (j = tid&127, c = tid>>7): rows {j, j+128}, k in [128c, 128c+128).
//   k[0:96) of window: fp32 weights in registers (48 ull per row).
//   k[96:128): fp16 weights in smem: wsh uint4 [cc][r2][g][j], g = group of
//   8 k (one uint4 = 8 halfs). 8 LDS.128/thread instead of 16.
// Dyn smem: wsh 32768 | h_buf 2048 | redA 512 | redB 512 = 35840 B.
// ---------------------------------------------------------------------------
__global__ __launch_bounds__(256, 1)
void rnn_step_kernel(const float* __restrict__ w_hh_f,
                     const float* __restrict__ w_hh_b,
                     float* __restrict__ out)
{
    extern __shared__ __align__(16) char smem_raw[];
    uint4* wsh    = (uint4*)smem_raw;                     // [2][2][4][128]
    float* h_buf  = (float*)(smem_raw + 32768);           // [2][256]
    float* redA   = h_buf + 512;                          // [128] c1 partials (row j)
    float* redB   = redA + 128;                           // [128] c0 partials (row j+128)

    const int id  = blockIdx.x;
    const int d   = id >> 6;
    const int b   = id & 63;
    const int tid = threadIdx.x;
    const int j   = tid & 127;
    const int c   = tid >> 7;

    const float* __restrict__ w_hh = d ? w_hh_b : w_hh_f;

    // --- fill fp16 streamed weights:
    // wsh[((cc*2+r2)*4+g)*128 + jj] = half8 of w[r2*128+jj][cc*128+96+8g .. +7]
    for (int i = tid; i < 2048; i += 256) {
        int jj = i & 127, g = (i >> 7) & 3, r2 = (i >> 9) & 1, cc = (i >> 10) & 1;
        const float* src = w_hh + (size_t)((r2 << 7) + jj) * 256
                                + (cc << 7) + 96 + (g << 3);
        float4 qa = *(const float4*)src;
        float4 qb = *(const float4*)(src + 4);
        wsh[i] = make_uint4(f2h2(qa.x, qa.y), f2h2(qa.z, qa.w),
                            f2h2(qb.x, qb.y), f2h2(qb.z, qb.w));
    }

    // --- register weights: rows j and j+128, k in [128c, 128c+96)
    unsigned long long w0[48], w1[48];
    {
        const float4* p0 = (const float4*)(w_hh + (size_t)j * 256 + (c << 7));
        const float4* p1 = (const float4*)(w_hh + (size_t)(j + 128) * 256 + (c << 7));
#pragma unroll
        for (int q = 0; q < 24; q++) {
            float4 v0 = p0[q], v1 = p1[q];
            w0[2 * q]     = pack2(v0.x, v0.y);
            w0[2 * q + 1] = pack2(v0.z, v0.w);
            w1[2 * q]     = pack2(v1.x, v1.y);
            w1[2 * q + 1] = pack2(v1.z, v1.w);
        }
    }

    // zero initial h
    h_buf[tid] = 0.0f;          // buffer 0 = h_buf[0..255]
    __syncthreads();

    const float* pre_base = g_pre + (size_t)d * (512 * 64 * 256);
    const int myrow = c ? (j + 128) : j;     // row this thread finishes
    float pre_cur;
    {
        int t0 = d ? 511 : 0;
        pre_cur = pre_base[((size_t)t0 * 64 + b) * 256 + myrow];
    }

    // streamed fp16 weight bases (rows j, j+128; this c); stride per g = 128
    const uint4* wh_r0 = wsh + ((c * 2 + 0) * 4) * 128 + j;
    const uint4* wh_r1 = wsh + ((c * 2 + 1) * 4) * 128 + j;

    for (int s = 0; s < 512; s++) {
        const int cur = s & 1, nxt = cur ^ 1;
        const int t = d ? (511 - s) : s;

        // prefetch next pre
        float pre_nxt = 0.0f;
        if (s < 511) {
            int t2 = d ? (510 - s) : (s + 1);
            pre_nxt = pre_base[((size_t)t2 * 64 + b) * 256 + myrow];
        }

        const ulonglong2* hb = (const ulonglong2*)(h_buf + (cur << 8) + (c << 7));

        unsigned long long a0 = 0ull, a1 = 0ull;
        // register-weight part: k-quads 0..23
#pragma unroll
        for (int q = 0; q < 24; q++) {
            ulonglong2 h2 = hb[q];
            a0 = ffma2(w0[2 * q],     h2.x, a0);
            a0 = ffma2(w0[2 * q + 1], h2.y, a0);
            a1 = ffma2(w1[2 * q],     h2.x, a1);
            a1 = ffma2(w1[2 * q + 1], h2.y, a1);
        }
        // fp16 streamed part: groups of 8 k (quads 24..31)
#pragma unroll
        for (int g = 0; g < 4; g++) {
            ulonglong2 hA = hb[24 + 2 * g];
            ulonglong2 hB = hb[24 + 2 * g + 1];
            uint4 wv0 = wh_r0[g * 128];
            uint4 wv1 = wh_r1[g * 128];
            a0 = ffma2(h2f2(wv0.x), hA.x, a0);
            a0 = ffma2(h2f2(wv0.y), hA.y, a0);
            a0 = ffma2(h2f2(wv0.z), hB.x, a0);
            a0 = ffma2(h2f2(wv0.w), hB.y, a0);
            a1 = ffma2(h2f2(wv1.x), hA.x, a1);
            a1 = ffma2(h2f2(wv1.y), hA.y, a1);
            a1 = ffma2(h2f2(wv1.z), hB.x, a1);
            a1 = ffma2(h2f2(wv1.w), hB.y, a1);
        }
        float p0 = sum2(a0);       // partial for row j     (this c's k-window)
        float p1 = sum2(a1);       // partial for row j+128

        if (c == 0) redB[j] = p1; else redA[j] = p0;
        __syncthreads();

        float v = c ? (p1 + redB[j]) : (p0 + redA[j]);
        float hv = fast_tanh(v + pre_cur);
        h_buf[(nxt << 8) + myrow] = hv;
        out[(((size_t)b << 9) + t) * 512 + (d << 8) + myrow] = hv;
        if (s == 511)
            out[OUT_YS + (((d << 6) + b) << 8) + myrow] = hv;
        pre_cur = pre_nxt;
        __syncthreads();
    }
}

// ---------------------------------------------------------------------------
extern "C" void kernel_launch(void* const* d_in, const int* in_sizes, int n_in,
                              void* d_out, int out_size) {
    const float* x      = (const float*)d_in[0];
    const float* w_ih_f = (const float*)d_in[1];
    const float* w_hh_f = (const float*)d_in[2];
    const float* b_ih_f = (const float*)d_in[3];
    const float* b_hh_f = (const float*)d_in[4];
    const float* w_ih_b = (const float*)d_in[5];
    const float* w_hh_b = (const float*)d_in[6];
    const float* b_ih_b = (const float*)d_in[7];
    const float* b_hh_b = (const float*)d_in[8];
    float* out = (float*)d_out;

    cudaFuncSetAttribute(pre_gemm_kernel,
                         cudaFuncAttributeMaxDynamicSharedMemorySize, GEMM_SMEM);
    cudaFuncSetAttribute(rnn_step_kernel,
                         cudaFuncAttributeMaxDynamicSharedMemorySize, STEP_SMEM);

    pre_gemm_kernel<<<1024, 256, GEMM_SMEM>>>(x, w_ih_f, b_ih_f, b_hh_f,
                                              w_ih_b, b_ih_b, b_hh_b);
    rnn_step_kernel<<<128, 256, STEP_SMEM>>>(w_hh_f, w_hh_b, out);
}

// round 17
// speedup vs baseline: 1.8667x; 1.2459x over previous
#include <cuda_runtime.h>
#include <cuda_bf16.h>
#include <cuda_fp16.h>
#include <cstdint>

// TorchBiRNN: B=64, T=512, I=128, H=256 bidirectional tanh RNN.
// Phase 1: pre GEMM v4 (R14, unchanged).
// Phase 2: HMMA step kernel (mma.sync m16n8k16 — baseline PTX, valid on
//          sm_103). One CTA per (batch,dir); W fp16 stationary in registers
//          as A-fragments; h fp16 in smem replicated across N columns;
//          one __syncthreads per step; no mbarrier/tcgen05.

#define OUT_YS (64 * 512 * 512)
#define GEMM_SMEM 131072

__device__ float g_pre[2 * 512 * 64 * 256];   // 64 MB scratch (module-static)

// ---------------- helpers ----------------
__device__ __forceinline__ unsigned long long ffma2(unsigned long long a,
                                                    unsigned long long b,
                                                    unsigned long long c) {
    unsigned long long d;
    asm("fma.rn.f32x2 %0, %1, %2, %3;" : "=l"(d) : "l"(a), "l"(b), "l"(c));
    return d;
}
__device__ __forceinline__ float sum2(unsigned long long v) {
    float2 f;
    asm("mov.b64 {%0, %1}, %2;" : "=f"(f.x), "=f"(f.y) : "l"(v));
    return f.x + f.y;
}
__device__ __forceinline__ float fast_tanh(float x) {
    float e = __expf(2.0f * x);
    return 1.0f - __fdividef(2.0f, e + 1.0f);
}
__device__ __forceinline__ uint32_t f2h2(float a, float b) {
    __half2 v = __floats2half2_rn(a, b);
    return *reinterpret_cast<uint32_t*>(&v);
}
__device__ __forceinline__ uint32_t s2u32(const void* p) {
    return (uint32_t)__cvta_generic_to_shared((void*)p);
}
__device__ __forceinline__ void cp_async16(uint32_t dst, const void* src) {
    asm volatile("cp.async.cg.shared.global [%0], [%1], 16;"
                 :: "r"(dst), "l"(src) : "memory");
}
#define CP_COMMIT() asm volatile("cp.async.commit_group;" ::: "memory")
#define CP_WAIT(n)  asm volatile("cp.async.wait_group %0;" :: "n"(n) : "memory")

// mma.sync m16n8k16 row.col f32 = f16*f16 + f32 (accumulate in place)
#define MMA16816(d, a, b)                                                     \
    asm volatile(                                                             \
        "mma.sync.aligned.m16n8k16.row.col.f32.f16.f16.f32 "                  \
        "{%0,%1,%2,%3}, {%4,%5,%6,%7}, {%8,%9}, {%0,%1,%2,%3};"               \
        : "+f"((d)[0]), "+f"((d)[1]), "+f"((d)[2]), "+f"((d)[3])              \
        : "r"((a)[0]), "r"((a)[1]), "r"((a)[2]), "r"((a)[3]),                 \
          "r"((b)[0]), "r"((b)[1]))

// ---------------------------------------------------------------------------
// Phase 1: GEMM v4 (unchanged from R14). 128x128 tile, 8x8 microtile,
// K in 4 chunks of 32 via cp.async 2-deep pipeline. Grid 1024, occ 1.
// ---------------------------------------------------------------------------
__global__ __launch_bounds__(256) void pre_gemm_kernel(
    const float* __restrict__ x,
    const float* __restrict__ w_ih_f, const float* __restrict__ b_ih_f,
    const float* __restrict__ b_hh_f,
    const float* __restrict__ w_ih_b, const float* __restrict__ b_ih_b,
    const float* __restrict__ b_hh_b)
{
    extern __shared__ __align__(16) float4 smem4[];
    float4* xs4 = smem4;            // [4][128][8]
    float4* ws4 = smem4 + 4096;     // [4][128][8]

    const int bx = blockIdx.x;
    const int d  = bx >> 9;
    const int r9 = bx & 511;
    const int mt = r9 >> 1;
    const int nt = r9 & 1;
    const float* __restrict__ w_ih = d ? w_ih_b : w_ih_f;
    const float* __restrict__ bi   = d ? b_ih_b : b_ih_f;
    const float* __restrict__ bh   = d ? b_hh_b : b_hh_f;
    const int m0 = mt << 7, n0 = nt << 7;
    const int tid = threadIdx.x;
    const int tm = tid & 15, tn = tid >> 4;

    const uint32_t xs_u = s2u32(xs4);
    const uint32_t ws_u = s2u32(ws4);

    auto load_chunk = [&](int ch) {
#pragma unroll
        for (int i = 0; i < 4; i++) {
            int idx = tid + (i << 8);
            int r = idx >> 3, kf4 = idx & 7;
            int sw = kf4 ^ ((r >> 3) & 7);
            uint32_t off = (uint32_t)(ch * 1024 + (r << 3) + sw) << 4;
            int m = m0 + r;
            int t = m >> 6, bb = m & 63;
            cp_async16(xs_u + off,
                       x + ((size_t)(bb << 9) + t) * 128 + (ch << 5) + (kf4 << 2));
            cp_async16(ws_u + off,
                       w_ih + ((size_t)(n0 + r) << 7) + (ch << 5) + (kf4 << 2));
        }
        CP_COMMIT();
    };

    load_chunk(0);
    load_chunk(1);

    unsigned long long acc[8][8];
#pragma unroll
    for (int m = 0; m < 8; m++)
#pragma unroll
        for (int n = 0; n < 8; n++) acc[m][n] = 0ull;

#pragma unroll
    for (int ch = 0; ch < 4; ch++) {
        if (ch < 3) CP_WAIT(1); else CP_WAIT(0);
        __syncthreads();
        if (ch < 2) load_chunk(ch + 2);

#pragma unroll
        for (int k4 = 0; k4 < 8; k4++) {
            ulonglong2 a2[8], b2[8];
#pragma unroll
            for (int m = 0; m < 8; m++)
                a2[m] = *(const ulonglong2*)&xs4[ch * 1024 + (((tm << 3) + m) << 3)
                                                 + (k4 ^ (tm & 7))];
#pragma unroll
            for (int n = 0; n < 8; n++)
                b2[n] = *(const ulonglong2*)&ws4[ch * 1024 + (((tn << 3) + n) << 3)
                                                 + (k4 ^ (tn & 7))];
#pragma unroll
            for (int m = 0; m < 8; m++)
#pragma unroll
                for (int n = 0; n < 8; n++) {
                    acc[m][n] = ffma2(a2[m].x, b2[n].x, acc[m][n]);
                    acc[m][n] = ffma2(a2[m].y, b2[n].y, acc[m][n]);
                }
        }
    }

    const int nbase = n0 + (tn << 3);
    float4 biL = *(const float4*)(bi + nbase);
    float4 biH = *(const float4*)(bi + nbase + 4);
    float4 bhL = *(const float4*)(bh + nbase);
    float4 bhH = *(const float4*)(bh + nbase + 4);
    float4 bL, bH;
    bL.x = biL.x + bhL.x; bL.y = biL.y + bhL.y;
    bL.z = biL.z + bhL.z; bL.w = biL.w + bhL.w;
    bH.x = biH.x + bhH.x; bH.y = biH.y + bhH.y;
    bH.z = biH.z + bhH.z; bH.w = biH.w + bhH.w;

#pragma unroll
    for (int m = 0; m < 8; m++) {
        int mrow = m0 + (tm << 3) + m;
        float* op = g_pre + ((size_t)(d * 32768 + mrow)) * 256 + nbase;
        float4 oL, oH;
        oL.x = sum2(acc[m][0]) + bL.x;
        oL.y = sum2(acc[m][1]) + bL.y;
        oL.z = sum2(acc[m][2]) + bL.z;
        oL.w = sum2(acc[m][3]) + bL.w;
        oH.x = sum2(acc[m][4]) + bH.x;
        oH.y = sum2(acc[m][5]) + bH.y;
        oH.z = sum2(acc[m][6]) + bH.z;
        oH.w = sum2(acc[m][7]) + bH.w;
        *(float4*)op = oL;
        *(float4*)(op + 4) = oH;
    }
}

// ---------------------------------------------------------------------------
// Phase 2: HMMA recurrence. Grid 128 (one CTA per (batch,dir)), 256 threads.
// Warp w owns output rows [32w, 32w+32) as two m16 tiles. A-fragments (W,
// fp16) prebuilt in registers: 2 mt x 16 kt x 4 regs = 128 regs/thread.
// B-fragment: h (fp16, smem, double-buffered) at k = 16kt + (lane%4)*2 and
// +8 — independent of lane/4 => all 8 N columns replicate h, D cols all = y.
// 4 accumulator chains (even/odd kt per tile). Epilogue: lane l owns row
// 32w + 8*(l%4) + l/4, value in its own fragment regs. One sync per step.
// ---------------------------------------------------------------------------
__global__ __launch_bounds__(256, 1)
void rnn_step_kernel(const float* __restrict__ w_hh_f,
                     const float* __restrict__ w_hh_b,
                     float* __restrict__ out)
{
    __shared__ __align__(16) __half h_buf[2][256];

    const int id   = blockIdx.x;
    const int d    = id >> 6;
    const int b    = id & 63;
    const int tid  = threadIdx.x;
    const int wid  = tid >> 5;
    const int lane = tid & 31;
    const int lq   = lane >> 2;      // lane/4: 0..7
    const int lr   = lane & 3;       // lane%4: 0..3

    const float* __restrict__ w_hh = d ? w_hh_b : w_hh_f;

    // --- build A fragments: wa[(mt*16+kt)*4 + r]
    uint32_t wa[128];
    {
#pragma unroll
        for (int mt = 0; mt < 2; mt++) {
            const int row = (wid << 5) + (mt << 4) + lq;
            const float* W0 = w_hh + (size_t)row * 256;
            const float* W8 = W0 + 8 * 256;
#pragma unroll
            for (int kt = 0; kt < 16; kt++) {
                const int col = (kt << 4) + (lr << 1);
                float2 v0 = *(const float2*)(W0 + col);
                float2 v1 = *(const float2*)(W8 + col);
                float2 v2 = *(const float2*)(W0 + col + 8);
                float2 v3 = *(const float2*)(W8 + col + 8);
                const int base = ((mt << 4) + kt) << 2;
                wa[base + 0] = f2h2(v0.x, v0.y);
                wa[base + 1] = f2h2(v1.x, v1.y);
                wa[base + 2] = f2h2(v2.x, v2.y);
                wa[base + 3] = f2h2(v3.x, v3.y);
            }
        }
    }

    // zero initial h (both buffers)
    h_buf[0][tid] = __float2half_rn(0.0f);
    h_buf[1][tid] = __float2half_rn(0.0f);
    __syncthreads();

    // row this thread owns in the epilogue
    const int myrow = (wid << 5) + (lr << 3) + lq;
    const float* pre_ptr = g_pre + (size_t)d * (512 * 64 * 256)
                         + ((size_t)(d ? 511 : 0) * 64 + b) * 256 + myrow;
    const ptrdiff_t pre_stride = d ? -(ptrdiff_t)(64 * 256) : (ptrdiff_t)(64 * 256);
    float* out_ptr = out + (((size_t)b << 9) + (d ? 511 : 0)) * 512 + (d << 8) + myrow;
    const ptrdiff_t out_stride = d ? -(ptrdiff_t)512 : (ptrdiff_t)512;
    float pre_cur = *pre_ptr;
    pre_ptr += pre_stride;

    for (int s = 0; s < 512; s++) {
        const int cur = s & 1, nxt = cur ^ 1;

        // prefetch next pre (in flight across the MMAs)
        float pre_nxt = 0.0f;
        if (s < 511) { pre_nxt = *pre_ptr; pre_ptr += pre_stride; }

        const __half* hc = h_buf[cur];

        float d0a[4] = {0.f, 0.f, 0.f, 0.f};   // tile0, even kt
        float d0b[4] = {0.f, 0.f, 0.f, 0.f};   // tile0, odd kt
        float d1a[4] = {0.f, 0.f, 0.f, 0.f};   // tile1, even kt
        float d1b[4] = {0.f, 0.f, 0.f, 0.f};   // tile1, odd kt

#pragma unroll
        for (int kt = 0; kt < 16; kt++) {
            const int k = (kt << 4) + (lr << 1);
            uint32_t bfrag[2];
            bfrag[0] = *(const uint32_t*)(hc + k);       // h[k], h[k+1]
            bfrag[1] = *(const uint32_t*)(hc + k + 8);   // h[k+8], h[k+9]
            if (kt & 1) {
                MMA16816(d0b, &wa[(kt) << 2],        bfrag);
                MMA16816(d1b, &wa[(16 + kt) << 2],   bfrag);
            } else {
                MMA16816(d0a, &wa[(kt) << 2],        bfrag);
                MMA16816(d1a, &wa[(16 + kt) << 2],   bfrag);
            }
        }

        // lane's own row value: sel by lane%4 over {t0c0, t0c2, t1c0, t1c2}
        float v;
        if      (lr == 0) v = d0a[0] + d0b[0];
        else if (lr == 1) v = d0a[2] + d0b[2];
        else if (lr == 2) v = d1a[0] + d1b[0];
        else              v = d1a[2] + d1b[2];

        float hv = fast_tanh(v + pre_cur);
        h_buf[nxt][myrow] = __float2half_rn(hv);

        const int t = d ? (511 - s) : s;
        (void)t;
        *out_ptr = hv;
        out_ptr += out_stride;
        if (s == 511)
            out[OUT_YS + (((d << 6) + b) << 8) + myrow] = hv;
        pre_cur = pre_nxt;

        __syncthreads();   // publish h[nxt]; all B-fragment reads of h[cur] done
    }
}

// ---------------------------------------------------------------------------
extern "C" void kernel_launch(void* const* d_in, const int* in_sizes, int n_in,
                              void* d_out, int out_size) {
    const float* x      = (const float*)d_in[0];
    const float* w_ih_f = (const float*)d_in[1];
    const float* w_hh_f = (const float*)d_in[2];
    const float* b_ih_f = (const float*)d_in[3];
    const float* b_hh_f = (const float*)d_in[4];
    const float* w_ih_b = (const float*)d_in[5];
    const float* w_hh_b = (const float*)d_in[6];
    const float* b_ih_b = (const float*)d_in[7];
    const float* b_hh_b = (const float*)d_in[8];
    float* out = (float*)d_out;

    cudaFuncSetAttribute(pre_gemm_kernel,
                         cudaFuncAttributeMaxDynamicSharedMemorySize, GEMM_SMEM);

    pre_gemm_kernel<<<1024, 256, GEMM_SMEM>>>(x, w_ih_f, b_ih_f, b_hh_f,
                                              w_ih_b, b_ih_b, b_hh_b);
    rnn_step_kernel<<<128, 256>>>(w_hh_f, w_hh_b, out);
}